// round 7
// baseline (speedup 1.0000x reference)
#include <cuda_runtime.h>
#include <cuda_fp16.h>
#include <cstdint>

#define NB 8
#define LC 2048
#define LQ 512
#define DD 768
#define NSM_CTAS 296   // 148 SMs x 2 CTAs

// ------------------------- device scratch (static) -------------------------
__device__ float g_tmp[NB * LC * LQ];                      // logits [b][c][q]
__device__ __align__(16) __half g_ctx_hi[NB * LC * DD];
__device__ __align__(16) __half g_ctx_lo[NB * LC * DD];
__device__ __align__(16) __half g_qry_hi[NB * LQ * DD];
__device__ __align__(16) __half g_qry_lo[NB * LQ * DD];
__device__ __align__(16) __half g_qryT_hi[NB * DD * LQ];   // [b][d][q]
__device__ __align__(16) __half g_qryT_lo[NB * DD * LQ];
__device__ __align__(16) __half g_alpha_hi[NB * LC * LQ];  // [b][c][q]

// ------------------------- helpers -------------------------
__device__ __forceinline__ uint32_t smem_u32(const void* p) {
    uint32_t a;
    asm("{ .reg .u64 t; cvta.to.shared.u64 t, %1; cvt.u32.u64 %0, t; }" : "=r"(a) : "l"(p));
    return a;
}
__device__ __forceinline__ void cpa16(uint32_t s, const void* g) {
    asm volatile("cp.async.cg.shared.global [%0], [%1], 16;" :: "r"(s), "l"(g));
}
#define CP_COMMIT() asm volatile("cp.async.commit_group;" ::: "memory")
#define CP_WAIT0()  asm volatile("cp.async.wait_group 0;" ::: "memory")
#define CP_WAIT1()  asm volatile("cp.async.wait_group 1;" ::: "memory")

__device__ __forceinline__ void ldsm4(uint32_t* r, uint32_t addr) {
    asm volatile("ldmatrix.sync.aligned.m8n8.x4.shared.b16 {%0,%1,%2,%3}, [%4];"
                 : "=r"(r[0]), "=r"(r[1]), "=r"(r[2]), "=r"(r[3]) : "r"(addr));
}
__device__ __forceinline__ void mma16816(float* d, const uint32_t* a,
                                         const uint32_t b0, const uint32_t b1) {
    asm volatile(
        "mma.sync.aligned.m16n8k16.row.col.f32.f16.f16.f32 "
        "{%0,%1,%2,%3}, {%4,%5,%6,%7}, {%8,%9}, {%0,%1,%2,%3};"
        : "+f"(d[0]), "+f"(d[1]), "+f"(d[2]), "+f"(d[3])
        : "r"(a[0]), "r"(a[1]), "r"(a[2]), "r"(a[3]), "r"(b0), "r"(b1));
}

// Swizzled byte offset inside a 128-row x 32-col(fp16) tile (64B rows, 16B chunks)
__device__ __forceinline__ uint32_t swoff(int r, int c) {
    return (uint32_t)((r * 4 + (c ^ ((r >> 1) & 3))) << 4);
}

// fp16 split
__device__ __forceinline__ void split2h(float x, __half& h, __half& l) {
    h = __float2half_rn(x);
    l = __float2half_rn(x - __half2float(h));
}
__device__ __forceinline__ uint32_t pkh(__half a, __half b) {
    uint16_t x = *(uint16_t*)&a, y = *(uint16_t*)&b;
    return (uint32_t)x | ((uint32_t)y << 16);
}

// ------------------------- conversion kernels -------------------------
__global__ __launch_bounds__(256) void k_split_ctx(const float* __restrict__ in) {
    int i = blockIdx.x * 256 + threadIdx.x;
    float4 v = ((const float4*)in)[i];
    __half h0, h1, h2, h3, l0, l1, l2, l3;
    split2h(v.x, h0, l0); split2h(v.y, h1, l1);
    split2h(v.z, h2, l2); split2h(v.w, h3, l3);
    ((uint2*)g_ctx_hi)[i] = make_uint2(pkh(h0, h1), pkh(h2, h3));
    ((uint2*)g_ctx_lo)[i] = make_uint2(pkh(l0, l1), pkh(l2, l3));
}

// Fused: split qry (row-major) AND produce transposed split copies.
__global__ __launch_bounds__(256) void k_split_qry_both(const float* __restrict__ qry) {
    __shared__ float t[32][33];
    int b = blockIdx.z;
    int d0 = blockIdx.x * 32, q0 = blockIdx.y * 32;
    int tx = threadIdx.x & 31, ty = threadIdx.x >> 5;
    const float* src = qry + (size_t)b * LQ * DD;
#pragma unroll
    for (int i = 0; i < 4; ++i) {
        int q = q0 + ty + 8 * i;
        float v = src[(size_t)q * DD + d0 + tx];
        t[ty + 8 * i][tx] = v;
        __half h, l;
        split2h(v, h, l);
        size_t o = (size_t)(b * LQ + q) * DD + d0 + tx;
        g_qry_hi[o] = h;
        g_qry_lo[o] = l;
    }
    __syncthreads();
#pragma unroll
    for (int i = 0; i < 4; ++i) {
        int d = d0 + ty + 8 * i;
        float v = t[tx][ty + 8 * i];
        __half h, l;
        split2h(v, h, l);
        size_t o = ((size_t)b * DD + d) * LQ + q0 + tx;
        g_qryT_hi[o] = h;
        g_qryT_lo[o] = l;
    }
}

// ------------------------- GEMM core -------------------------
// CTA 128x128, 4 warps (2x2), warp tile 64x64, BK=32, 3-stage cp.async.
template <bool ASPLIT>
struct Lay {
    static constexpr int OAH = 0;
    static constexpr int OAL = ASPLIT ? 8192 : 0;
    static constexpr int OBH = ASPLIT ? 16384 : 8192;
    static constexpr int OBL = OBH + 8192;
    static constexpr int STG = OBL + 8192;   // 32K (split A) or 24K
};

template <bool ASPLIT>
__device__ __forceinline__ void load_chunk(uint32_t sb,
                                           const __half* __restrict__ Ah,
                                           const __half* __restrict__ Al,
                                           const __half* __restrict__ Bh,
                                           const __half* __restrict__ Bl,
                                           int astr, int bstr, int k0, int tid) {
    using L = Lay<ASPLIT>;
#pragma unroll
    for (int i = 0; i < 4; ++i) {
        int u = tid + i * 128;          // 0..511
        int r = u >> 2, c = u & 3;
        uint32_t sw = swoff(r, c);
        size_t ao = (size_t)r * astr + k0 + c * 8;
        size_t bo = (size_t)r * bstr + k0 + c * 8;
        cpa16(sb + L::OAH + sw, Ah + ao);
        if (ASPLIT) cpa16(sb + L::OAL + sw, Al + ao);
        cpa16(sb + L::OBH + sw, Bh + bo);
        cpa16(sb + L::OBL + sw, Bl + bo);
    }
}

// Per-tile mainloop. Pipeline restarts each tile; caller must __syncthreads
// before calling (protects stage reuse across tiles).
template <bool ASPLIT>
__device__ __forceinline__ void mma_mainloop(float (&acc)[4][8][4], uint32_t sb,
                                             const __half* __restrict__ Ah,
                                             const __half* __restrict__ Al,
                                             const __half* __restrict__ Bh,
                                             const __half* __restrict__ Bl,
                                             int astr, int bstr, int nch, int tid) {
    using L = Lay<ASPLIT>;
    const int wid = tid >> 5, l = tid & 31;
    const int wm = (wid & 1) * 64, wn = (wid >> 1) * 64;
    const int a_row = wm + (l & 15);
    const int a_ch = (l >> 4) & 1;
    const int b_row = wn + (l & 7) + ((l >> 4) << 3);
    const int b_ch = (l >> 3) & 1;

    load_chunk<ASPLIT>(sb, Ah, Al, Bh, Bl, astr, bstr, 0, tid);
    CP_COMMIT();
    load_chunk<ASPLIT>(sb + L::STG, Ah, Al, Bh, Bl, astr, bstr, 32, tid);
    CP_COMMIT();

    int stage = 0;
    for (int ch = 0; ch < nch; ++ch) {
        if (ch + 1 < nch) CP_WAIT1(); else CP_WAIT0();
        __syncthreads();
        if (ch + 2 < nch) {
            int ns = stage + 2; if (ns >= 3) ns -= 3;
            load_chunk<ASPLIT>(sb + ns * L::STG, Ah, Al, Bh, Bl, astr, bstr, (ch + 2) * 32, tid);
            CP_COMMIT();
        }

        uint32_t s = sb + stage * L::STG;
#pragma unroll
        for (int kk = 0; kk < 2; ++kk) {
            uint32_t ah[16], al[16];
#pragma unroll
            for (int mt = 0; mt < 4; ++mt) {
                uint32_t off = swoff(a_row + mt * 16, kk * 2 + a_ch);
                ldsm4(&ah[mt * 4], s + L::OAH + off);
                if (ASPLIT) ldsm4(&al[mt * 4], s + L::OAL + off);
            }
            uint32_t bh[16], bl[16];
#pragma unroll
            for (int g = 0; g < 4; ++g) {
                uint32_t off = swoff(b_row + g * 16, kk * 2 + b_ch);
                ldsm4(&bh[g * 4], s + L::OBH + off);
                ldsm4(&bl[g * 4], s + L::OBL + off);
            }
#pragma unroll
            for (int mt = 0; mt < 4; ++mt)
#pragma unroll
                for (int nt = 0; nt < 8; ++nt)
                    mma16816(acc[mt][nt], &ah[mt * 4], bh[nt * 2], bh[nt * 2 + 1]);
#pragma unroll
            for (int mt = 0; mt < 4; ++mt)
#pragma unroll
                for (int nt = 0; nt < 8; ++nt)
                    mma16816(acc[mt][nt], &ah[mt * 4], bl[nt * 2], bl[nt * 2 + 1]);
            if (ASPLIT) {
#pragma unroll
                for (int mt = 0; mt < 4; ++mt)
#pragma unroll
                    for (int nt = 0; nt < 8; ++nt)
                        mma16816(acc[mt][nt], &al[mt * 4], bh[nt * 2], bh[nt * 2 + 1]);
            }
        }
        ++stage; if (stage == 3) stage = 0;
    }
}

// ------------------------- GEMM1: logits (persistent) ---------------------
#define NT1 (4 * 16 * NB)   // 512 tiles: n(4) x m(16) x b(8)

__global__ __launch_bounds__(128, 2) void k_gemm1_mma() {
    extern __shared__ char smem[];
    uint32_t sb = smem_u32(smem);
    const int tid = threadIdx.x;
    const int wid = tid >> 5, l = tid & 31;
    const int wm = (wid & 1) * 64, wn = (wid >> 1) * 64;

    for (int t = blockIdx.x; t < NT1; t += NSM_CTAS) {
        const int b = t >> 6;
        const int m0 = ((t >> 2) & 15) * 128;
        const int n0 = (t & 3) * 128;

        float acc[4][8][4];
#pragma unroll
        for (int i = 0; i < 4; ++i)
#pragma unroll
            for (int j = 0; j < 8; ++j)
#pragma unroll
                for (int k = 0; k < 4; ++k) acc[i][j][k] = 0.0f;

        __syncthreads();  // protect smem stages across tiles
        mma_mainloop<true>(acc, sb,
                           g_ctx_hi + ((size_t)b * LC + m0) * DD,
                           g_ctx_lo + ((size_t)b * LC + m0) * DD,
                           g_qry_hi + ((size_t)b * LQ + n0) * DD,
                           g_qry_lo + ((size_t)b * LQ + n0) * DD,
                           DD, DD, DD / 32, tid);

#pragma unroll
        for (int mt = 0; mt < 4; ++mt) {
#pragma unroll
            for (int nt = 0; nt < 8; ++nt) {
                int row = m0 + wm + mt * 16 + (l >> 2);
                int col = n0 + wn + nt * 8 + (l & 3) * 2;
                float* p0 = g_tmp + ((size_t)b * LC + row) * LQ + col;
                float* p1 = g_tmp + ((size_t)b * LC + row + 8) * LQ + col;
                *(float2*)p0 = make_float2(acc[mt][nt][0], acc[mt][nt][1]);
                *(float2*)p1 = make_float2(acc[mt][nt][2], acc[mt][nt][3]);
            }
        }
    }
}

// ------------------------- softmax over q (128 thr, float4) ---------------
__global__ __launch_bounds__(128) void k_softmax() {
    const int row = blockIdx.x;  // b*LC + c
    const float4* p = (const float4*)(g_tmp + (size_t)row * LQ);
    const int tid = threadIdx.x;

    float4 v = p[tid];
    float m = fmaxf(fmaxf(v.x, v.y), fmaxf(v.z, v.w));
#pragma unroll
    for (int o = 16; o > 0; o >>= 1) m = fmaxf(m, __shfl_xor_sync(0xffffffffu, m, o));

    __shared__ float smax[4];
    __shared__ float ssum[4];
    if ((tid & 31) == 0) smax[tid >> 5] = m;
    __syncthreads();
    float bm = fmaxf(fmaxf(smax[0], smax[1]), fmaxf(smax[2], smax[3]));

    float e0 = __expf(v.x - bm);
    float e1 = __expf(v.y - bm);
    float e2 = __expf(v.z - bm);
    float e3 = __expf(v.w - bm);
    float s = (e0 + e1) + (e2 + e3);
#pragma unroll
    for (int o = 16; o > 0; o >>= 1) s += __shfl_xor_sync(0xffffffffu, s, o);
    if ((tid & 31) == 0) ssum[tid >> 5] = s;
    __syncthreads();
    float bs = (ssum[0] + ssum[1]) + (ssum[2] + ssum[3]);

    float inv = 1.0f / bs;
    uint2 w = make_uint2(pkh(__float2half_rn(e0 * inv), __float2half_rn(e1 * inv)),
                         pkh(__float2half_rn(e2 * inv), __float2half_rn(e3 * inv)));
    ((uint2*)g_alpha_hi)[(size_t)row * (LQ / 4) + tid] = w;
}

// ------------------------- GEMM2 + gate (persistent) ----------------------
#define NT2 (6 * 16 * NB)   // 768 tiles: n(6) x m(16) x b(8)

__global__ __launch_bounds__(128, 2) void k_gemm2_mma(const float* __restrict__ ctx,
                                                      float* __restrict__ out) {
    extern __shared__ char smem[];
    uint32_t sb = smem_u32(smem);
    const int tid = threadIdx.x;
    const int wid = tid >> 5, l = tid & 31;
    const int wm = (wid & 1) * 64, wn = (wid >> 1) * 64;

    for (int t = blockIdx.x; t < NT2; t += NSM_CTAS) {
        const int b = t / 96;
        const int r = t % 96;
        const int m0 = (r / 6) * 128;
        const int n0 = (r % 6) * 128;

        float acc[4][8][4];
#pragma unroll
        for (int i = 0; i < 4; ++i)
#pragma unroll
            for (int j = 0; j < 8; ++j)
#pragma unroll
                for (int k = 0; k < 4; ++k) acc[i][j][k] = 0.0f;

        __syncthreads();  // protect smem stages across tiles
        mma_mainloop<false>(acc, sb,
                            g_alpha_hi + ((size_t)b * LC + m0) * LQ,
                            nullptr,
                            g_qryT_hi + ((size_t)b * DD + n0) * LQ,
                            g_qryT_lo + ((size_t)b * DD + n0) * LQ,
                            LQ, LQ, LQ / 32, tid);

#pragma unroll
        for (int mt = 0; mt < 4; ++mt) {
#pragma unroll
            for (int nt = 0; nt < 8; ++nt) {
                int row = m0 + wm + mt * 16 + (l >> 2);
                int col = n0 + wn + nt * 8 + (l & 3) * 2;
                size_t o0 = ((size_t)b * LC + row) * DD + col;
                size_t o1 = ((size_t)b * LC + row + 8) * DD + col;
                float2 c0 = *(const float2*)(ctx + o0);
                float2 c1 = *(const float2*)(ctx + o1);
                *(float2*)(out + o0) = make_float2(acc[mt][nt][0] * c0.x, acc[mt][nt][1] * c0.y);
                *(float2*)(out + o1) = make_float2(acc[mt][nt][2] * c1.x, acc[mt][nt][3] * c1.y);
            }
        }
    }
}

// ------------------------- launch -------------------------
extern "C" void kernel_launch(void* const* d_in, const int* in_sizes, int n_in,
                              void* d_out, int out_size) {
    (void)in_sizes; (void)n_in; (void)out_size;
    const float* ctx = (const float*)d_in[0];  // [8,2048,768]
    const float* qry = (const float*)d_in[1];  // [8,512,768]
    float* out = (float*)d_out;

    const int smem1 = 3 * Lay<true>::STG;   // 98304
    const int smem2 = 3 * Lay<false>::STG;  // 73728
    cudaFuncSetAttribute(k_gemm1_mma, cudaFuncAttributeMaxDynamicSharedMemorySize, smem1);
    cudaFuncSetAttribute(k_gemm2_mma, cudaFuncAttributeMaxDynamicSharedMemorySize, smem2);

    k_split_ctx<<<(NB * LC * DD) / (256 * 4), 256>>>(ctx);
    k_split_qry_both<<<dim3(DD / 32, LQ / 32, NB), 256>>>(qry);

    k_gemm1_mma<<<NSM_CTAS, 128, smem1>>>();
    k_softmax<<<NB * LC, 128>>>();
    k_gemm2_mma<<<NSM_CTAS, 128, smem2>>>(ctx, out);
}

// round 8
// speedup vs baseline: 1.1072x; 1.1072x over previous
#include <cuda_runtime.h>
#include <cuda_fp16.h>
#include <cstdint>

#define NB 8
#define LC 2048
#define LQ 512
#define DD 768

// ------------------------- device scratch (static) -------------------------
__device__ float g_tmp[NB * LC * LQ];                      // logits [b][c][q]
__device__ __align__(16) __half g_ctx_hi[NB * LC * DD];
__device__ __align__(16) __half g_ctx_lo[NB * LC * DD];
__device__ __align__(16) __half g_qry_hi[NB * LQ * DD];
__device__ __align__(16) __half g_qry_lo[NB * LQ * DD];
__device__ __align__(16) __half g_qryT_hi[NB * DD * LQ];   // [b][d][q]
__device__ __align__(16) __half g_alpha_hi[NB * LC * LQ];  // [b][c][q]

// ------------------------- helpers -------------------------
__device__ __forceinline__ uint32_t smem_u32(const void* p) {
    uint32_t a;
    asm("{ .reg .u64 t; cvta.to.shared.u64 t, %1; cvt.u32.u64 %0, t; }" : "=r"(a) : "l"(p));
    return a;
}
__device__ __forceinline__ void cpa16(uint32_t s, const void* g) {
    asm volatile("cp.async.cg.shared.global [%0], [%1], 16;" :: "r"(s), "l"(g));
}
#define CP_COMMIT() asm volatile("cp.async.commit_group;" ::: "memory")
#define CP_WAIT0()  asm volatile("cp.async.wait_group 0;" ::: "memory")
#define CP_WAIT1()  asm volatile("cp.async.wait_group 1;" ::: "memory")

__device__ __forceinline__ void ldsm4(uint32_t* r, uint32_t addr) {
    asm volatile("ldmatrix.sync.aligned.m8n8.x4.shared.b16 {%0,%1,%2,%3}, [%4];"
                 : "=r"(r[0]), "=r"(r[1]), "=r"(r[2]), "=r"(r[3]) : "r"(addr));
}
__device__ __forceinline__ void mma16816(float* d, const uint32_t* a,
                                         const uint32_t b0, const uint32_t b1) {
    asm volatile(
        "mma.sync.aligned.m16n8k16.row.col.f32.f16.f16.f32 "
        "{%0,%1,%2,%3}, {%4,%5,%6,%7}, {%8,%9}, {%0,%1,%2,%3};"
        : "+f"(d[0]), "+f"(d[1]), "+f"(d[2]), "+f"(d[3])
        : "r"(a[0]), "r"(a[1]), "r"(a[2]), "r"(a[3]), "r"(b0), "r"(b1));
}

// Swizzled byte offset inside a 128-row x 32-col(fp16) tile (64B rows, 16B chunks)
__device__ __forceinline__ uint32_t swoff(int r, int c) {
    return (uint32_t)((r * 4 + (c ^ ((r >> 1) & 3))) << 4);
}

// fp16 split
__device__ __forceinline__ void split2h(float x, __half& h, __half& l) {
    h = __float2half_rn(x);
    l = __float2half_rn(x - __half2float(h));
}
__device__ __forceinline__ uint32_t pkh(__half a, __half b) {
    uint16_t x = *(uint16_t*)&a, y = *(uint16_t*)&b;
    return (uint32_t)x | ((uint32_t)y << 16);
}

// ------------------------- conversion kernels -------------------------
__global__ __launch_bounds__(256) void k_split_ctx(const float* __restrict__ in) {
    int i = blockIdx.x * 256 + threadIdx.x;
    float4 v = ((const float4*)in)[i];
    __half h0, h1, h2, h3, l0, l1, l2, l3;
    split2h(v.x, h0, l0); split2h(v.y, h1, l1);
    split2h(v.z, h2, l2); split2h(v.w, h3, l3);
    ((uint2*)g_ctx_hi)[i] = make_uint2(pkh(h0, h1), pkh(h2, h3));
    ((uint2*)g_ctx_lo)[i] = make_uint2(pkh(l0, l1), pkh(l2, l3));
}

// Fused: split qry (row-major hi+lo) AND produce transposed hi copy.
__global__ __launch_bounds__(256) void k_split_qry_both(const float* __restrict__ qry) {
    __shared__ float t[32][33];
    int b = blockIdx.z;
    int d0 = blockIdx.x * 32, q0 = blockIdx.y * 32;
    int tx = threadIdx.x & 31, ty = threadIdx.x >> 5;
    const float* src = qry + (size_t)b * LQ * DD;
#pragma unroll
    for (int i = 0; i < 4; ++i) {
        int q = q0 + ty + 8 * i;
        float v = src[(size_t)q * DD + d0 + tx];
        t[ty + 8 * i][tx] = v;
        __half h, l;
        split2h(v, h, l);
        size_t o = (size_t)(b * LQ + q) * DD + d0 + tx;
        g_qry_hi[o] = h;
        g_qry_lo[o] = l;
    }
    __syncthreads();
#pragma unroll
    for (int i = 0; i < 4; ++i) {
        int d = d0 + ty + 8 * i;
        float v = t[tx][ty + 8 * i];
        size_t o = ((size_t)b * DD + d) * LQ + q0 + tx;
        g_qryT_hi[o] = __float2half_rn(v);
    }
}

// ------------------------- GEMM1: logits ---------------------------------
// CTA 128x128, 4 warps (2x2), warp 64x64, BK=32, 2-stage cp.async, 3 CTA/SM.
// smem per stage: Ah 8K, Al 8K, Bh 8K, Bl 8K = 32K; 2 stages = 64K.
#define G1_OAL 8192
#define G1_OBH 16384
#define G1_OBL 24576
#define G1_STG 32768

__device__ __forceinline__ void g1_load(uint32_t sb,
                                        const __half* __restrict__ Ah,
                                        const __half* __restrict__ Al,
                                        const __half* __restrict__ Bh,
                                        const __half* __restrict__ Bl,
                                        int k0, int tid) {
#pragma unroll
    for (int i = 0; i < 4; ++i) {
        int u = tid + i * 128;          // 0..511
        int r = u >> 2, c = u & 3;
        uint32_t sw = swoff(r, c);
        size_t ao = (size_t)r * DD + k0 + c * 8;
        cpa16(sb + sw, Ah + ao);
        cpa16(sb + G1_OAL + sw, Al + ao);
        cpa16(sb + G1_OBH + sw, Bh + ao);   // B stride also DD
        cpa16(sb + G1_OBL + sw, Bl + ao);
    }
}

__global__ __launch_bounds__(128, 3) void k_gemm1_mma() {
    extern __shared__ char smem[];
    uint32_t sb = smem_u32(smem);
    const int tid = threadIdx.x;
    const int wid = tid >> 5, l = tid & 31;
    const int wm = (wid & 1) * 64, wn = (wid >> 1) * 64;
    const int b = blockIdx.z, m0 = blockIdx.y * 128, n0 = blockIdx.x * 128;

    const __half* Ah = g_ctx_hi + ((size_t)b * LC + m0) * DD;
    const __half* Al = g_ctx_lo + ((size_t)b * LC + m0) * DD;
    const __half* Bh = g_qry_hi + ((size_t)b * LQ + n0) * DD;
    const __half* Bl = g_qry_lo + ((size_t)b * LQ + n0) * DD;

    const int a_row = wm + (l & 15);
    const int a_ch = (l >> 4) & 1;
    const int b_row0 = wn + (l & 7) + ((l >> 4) << 3);
    const int b_ch = (l >> 3) & 1;

    float acc[4][8][4];
#pragma unroll
    for (int i = 0; i < 4; ++i)
#pragma unroll
        for (int j = 0; j < 8; ++j)
#pragma unroll
            for (int k = 0; k < 4; ++k) acc[i][j][k] = 0.0f;

    g1_load(sb, Ah, Al, Bh, Bl, 0, tid);
    CP_COMMIT();

    const int nch = DD / 32;
    int stage = 0;
    for (int ch = 0; ch < nch; ++ch) {
        CP_WAIT0();
        __syncthreads();     // all warps done with the other stage
        if (ch + 1 < nch) {
            g1_load(sb + (stage ^ 1) * G1_STG, Ah, Al, Bh, Bl, (ch + 1) * 32, tid);
            CP_COMMIT();
        }
        uint32_t s = sb + stage * G1_STG;
#pragma unroll
        for (int kk = 0; kk < 2; ++kk) {
            // Phase 1: A-hi sweeps (hh + hl), B windowed per group
            uint32_t ah[16];
#pragma unroll
            for (int mt = 0; mt < 4; ++mt)
                ldsm4(&ah[mt * 4], s + swoff(a_row + mt * 16, kk * 2 + a_ch));
#pragma unroll
            for (int g = 0; g < 4; ++g) {
                uint32_t bh[4], bl[4];
                uint32_t off = swoff(b_row0 + g * 16, kk * 2 + b_ch);
                ldsm4(bh, s + G1_OBH + off);
                ldsm4(bl, s + G1_OBL + off);
#pragma unroll
                for (int mt = 0; mt < 4; ++mt) {
                    mma16816(acc[mt][2 * g],     &ah[mt * 4], bh[0], bh[1]);
                    mma16816(acc[mt][2 * g + 1], &ah[mt * 4], bh[2], bh[3]);
                }
#pragma unroll
                for (int mt = 0; mt < 4; ++mt) {
                    mma16816(acc[mt][2 * g],     &ah[mt * 4], bl[0], bl[1]);
                    mma16816(acc[mt][2 * g + 1], &ah[mt * 4], bl[2], bl[3]);
                }
            }
            // Phase 2: A-lo sweep (lh), reload B-hi per group
            uint32_t al[16];
#pragma unroll
            for (int mt = 0; mt < 4; ++mt)
                ldsm4(&al[mt * 4], s + G1_OAL + swoff(a_row + mt * 16, kk * 2 + a_ch));
#pragma unroll
            for (int g = 0; g < 4; ++g) {
                uint32_t bh[4];
                ldsm4(bh, s + G1_OBH + swoff(b_row0 + g * 16, kk * 2 + b_ch));
#pragma unroll
                for (int mt = 0; mt < 4; ++mt) {
                    mma16816(acc[mt][2 * g],     &al[mt * 4], bh[0], bh[1]);
                    mma16816(acc[mt][2 * g + 1], &al[mt * 4], bh[2], bh[3]);
                }
            }
        }
        stage ^= 1;
    }

#pragma unroll
    for (int mt = 0; mt < 4; ++mt) {
#pragma unroll
        for (int nt = 0; nt < 8; ++nt) {
            int row = m0 + wm + mt * 16 + (l >> 2);
            int col = n0 + wn + nt * 8 + (l & 3) * 2;
            float* p0 = g_tmp + ((size_t)b * LC + row) * LQ + col;
            float* p1 = g_tmp + ((size_t)b * LC + row + 8) * LQ + col;
            *(float2*)p0 = make_float2(acc[mt][nt][0], acc[mt][nt][1]);
            *(float2*)p1 = make_float2(acc[mt][nt][2], acc[mt][nt][3]);
        }
    }
}

// ------------------------- softmax over q (128 thr, float4) ---------------
__global__ __launch_bounds__(128) void k_softmax() {
    const int row = blockIdx.x;  // b*LC + c
    const float4* p = (const float4*)(g_tmp + (size_t)row * LQ);
    const int tid = threadIdx.x;

    float4 v = p[tid];
    float m = fmaxf(fmaxf(v.x, v.y), fmaxf(v.z, v.w));
#pragma unroll
    for (int o = 16; o > 0; o >>= 1) m = fmaxf(m, __shfl_xor_sync(0xffffffffu, m, o));

    __shared__ float smax[4];
    __shared__ float ssum[4];
    if ((tid & 31) == 0) smax[tid >> 5] = m;
    __syncthreads();
    float bm = fmaxf(fmaxf(smax[0], smax[1]), fmaxf(smax[2], smax[3]));

    float e0 = __expf(v.x - bm);
    float e1 = __expf(v.y - bm);
    float e2 = __expf(v.z - bm);
    float e3 = __expf(v.w - bm);
    float s = (e0 + e1) + (e2 + e3);
#pragma unroll
    for (int o = 16; o > 0; o >>= 1) s += __shfl_xor_sync(0xffffffffu, s, o);
    if ((tid & 31) == 0) ssum[tid >> 5] = s;
    __syncthreads();
    float bs = (ssum[0] + ssum[1]) + (ssum[2] + ssum[3]);

    float inv = 1.0f / bs;
    uint2 w = make_uint2(pkh(__float2half_rn(e0 * inv), __float2half_rn(e1 * inv)),
                         pkh(__float2half_rn(e2 * inv), __float2half_rn(e3 * inv)));
    ((uint2*)g_alpha_hi)[(size_t)row * (LQ / 4) + tid] = w;
}

// ------------------------- GEMM2 + gate: single-term fp16 -----------------
// CTA 128x128, warp 64x64, BK=32, 3-stage, per stage A 8K + B 8K = 16K.
#define G2_OBH 8192
#define G2_STG 16384

__device__ __forceinline__ void g2_load(uint32_t sb,
                                        const __half* __restrict__ A,
                                        const __half* __restrict__ B,
                                        int k0, int tid) {
#pragma unroll
    for (int i = 0; i < 4; ++i) {
        int u = tid + i * 128;
        int r = u >> 2, c = u & 3;
        uint32_t sw = swoff(r, c);
        cpa16(sb + sw, A + (size_t)r * LQ + k0 + c * 8);
        cpa16(sb + G2_OBH + sw, B + (size_t)r * LQ + k0 + c * 8);
    }
}

__global__ __launch_bounds__(128, 3) void k_gemm2_mma(const float* __restrict__ ctx,
                                                      float* __restrict__ out) {
    extern __shared__ char smem[];
    uint32_t sb = smem_u32(smem);
    const int tid = threadIdx.x;
    const int wid = tid >> 5, l = tid & 31;
    const int wm = (wid & 1) * 64, wn = (wid >> 1) * 64;
    const int b = blockIdx.z, m0 = blockIdx.y * 128, n0 = blockIdx.x * 128;

    const __half* A = g_alpha_hi + ((size_t)b * LC + m0) * LQ;
    const __half* B = g_qryT_hi + ((size_t)b * DD + n0) * LQ;

    const int a_row = wm + (l & 15);
    const int a_ch = (l >> 4) & 1;
    const int b_row0 = wn + (l & 7) + ((l >> 4) << 3);
    const int b_ch = (l >> 3) & 1;

    float acc[4][8][4];
#pragma unroll
    for (int i = 0; i < 4; ++i)
#pragma unroll
        for (int j = 0; j < 8; ++j)
#pragma unroll
            for (int k = 0; k < 4; ++k) acc[i][j][k] = 0.0f;

    g2_load(sb, A, B, 0, tid);
    CP_COMMIT();
    g2_load(sb + G2_STG, A, B, 32, tid);
    CP_COMMIT();

    const int nch = LQ / 32;
    int stage = 0;
    for (int ch = 0; ch < nch; ++ch) {
        if (ch + 1 < nch) CP_WAIT1(); else CP_WAIT0();
        __syncthreads();
        if (ch + 2 < nch) {
            int ns = stage + 2; if (ns >= 3) ns -= 3;
            g2_load(sb + ns * G2_STG, A, B, (ch + 2) * 32, tid);
            CP_COMMIT();
        }
        uint32_t s = sb + stage * G2_STG;
#pragma unroll
        for (int kk = 0; kk < 2; ++kk) {
            uint32_t ah[16];
#pragma unroll
            for (int mt = 0; mt < 4; ++mt)
                ldsm4(&ah[mt * 4], s + swoff(a_row + mt * 16, kk * 2 + a_ch));
#pragma unroll
            for (int g = 0; g < 4; ++g) {
                uint32_t bh[4];
                ldsm4(bh, s + G2_OBH + swoff(b_row0 + g * 16, kk * 2 + b_ch));
#pragma unroll
                for (int mt = 0; mt < 4; ++mt) {
                    mma16816(acc[mt][2 * g],     &ah[mt * 4], bh[0], bh[1]);
                    mma16816(acc[mt][2 * g + 1], &ah[mt * 4], bh[2], bh[3]);
                }
            }
        }
        ++stage; if (stage == 3) stage = 0;
    }

#pragma unroll
    for (int mt = 0; mt < 4; ++mt) {
#pragma unroll
        for (int nt = 0; nt < 8; ++nt) {
            int row = m0 + wm + mt * 16 + (l >> 2);
            int col = n0 + wn + nt * 8 + (l & 3) * 2;
            size_t o0 = ((size_t)b * LC + row) * DD + col;
            size_t o1 = ((size_t)b * LC + row + 8) * DD + col;
            float2 c0 = *(const float2*)(ctx + o0);
            float2 c1 = *(const float2*)(ctx + o1);
            *(float2*)(out + o0) = make_float2(acc[mt][nt][0] * c0.x, acc[mt][nt][1] * c0.y);
            *(float2*)(out + o1) = make_float2(acc[mt][nt][2] * c1.x, acc[mt][nt][3] * c1.y);
        }
    }
}

// ------------------------- launch -------------------------
extern "C" void kernel_launch(void* const* d_in, const int* in_sizes, int n_in,
                              void* d_out, int out_size) {
    (void)in_sizes; (void)n_in; (void)out_size;
    const float* ctx = (const float*)d_in[0];  // [8,2048,768]
    const float* qry = (const float*)d_in[1];  // [8,512,768]
    float* out = (float*)d_out;

    const int smem1 = 2 * G1_STG;   // 65536
    const int smem2 = 3 * G2_STG;   // 49152
    cudaFuncSetAttribute(k_gemm1_mma, cudaFuncAttributeMaxDynamicSharedMemorySize, smem1);
    cudaFuncSetAttribute(k_gemm2_mma, cudaFuncAttributeMaxDynamicSharedMemorySize, smem2);

    k_split_ctx<<<(NB * LC * DD) / (256 * 4), 256>>>(ctx);
    k_split_qry_both<<<dim3(DD / 32, LQ / 32, NB), 256>>>(qry);

    k_gemm1_mma<<<dim3(LQ / 128, LC / 128, NB), 128, smem1>>>();
    k_softmax<<<NB * LC, 128>>>();
    k_gemm2_mma<<<dim3(DD / 128, LC / 128, NB), 128, smem2>>>(ctx, out);
}